// round 1
// baseline (speedup 1.0000x reference)
#include <cuda_runtime.h>
#include <cuda_bf16.h>
#include <math_constants.h>

// SupPixPool: out[b][c][k] = max over pixels p with spx[b][p]==k of img[b][c][p]
// B=4, C=64, H=W=512 (HW=262144), K=1024.
//
// Strategy: bias values by +128.0f so all stored floats are positive ->
// float ordering == signed-int-bit ordering -> single atomicMax(int*) per
// element. Per-block SMEM privatization over an 8-channel group (32KB),
// then merge partials into d_out (reused as the int accumulator) with
// global atomicMax, then decode (subtract bias) in place.

#define HW   (512 * 512)
#define KSEG 1024
#define CTOT 64
#define BTOT 4
#define CGRP 8            // channels per block
#define NCG  (CTOT / CGRP)
#define PB   16           // pixel-range blocks per (b, channel-group)
#define PIX_PER_BLK (HW / PB)   // 16384
#define BIAS 128.0f

__global__ void __launch_bounds__(256) sp_init_kernel(float* __restrict__ out) {
    int i = blockIdx.x * 256 + threadIdx.x;
    out[i] = -CUDART_INF_F;   // bits 0xFF800000: loses (as signed int) to any biased value
}

__global__ void __launch_bounds__(256) sp_main_kernel(const float* __restrict__ img,
                                                      const int*   __restrict__ spx,
                                                      int*         __restrict__ out) {
    __shared__ int sm[CGRP * KSEG];   // 32 KB

    #pragma unroll
    for (int i = threadIdx.x; i < CGRP * KSEG; i += 256)
        sm[i] = 0xFF800000;           // -inf bits
    __syncthreads();

    const int b  = blockIdx.z;
    const int cg = blockIdx.y;
    const int p0 = blockIdx.x * PIX_PER_BLK;

    const int*   spxb = spx + b * HW + p0;
    const float* imgb = img + ((size_t)(b * CTOT + cg * CGRP)) * HW + p0;

    // 256 threads x 4-wide vectors = 1024 pixels per iteration; 16 iterations.
    for (int it = 0; it < PIX_PER_BLK / 1024; ++it) {
        const int base = (it * 256 + threadIdx.x) * 4;
        const int4 s4 = *reinterpret_cast<const int4*>(spxb + base);

        #pragma unroll
        for (int c = 0; c < CGRP; ++c) {
            const float4 v = *reinterpret_cast<const float4*>(imgb + (size_t)c * HW + base);
            // ATOMS.MAX.S32 with per-channel immediate offset c*KSEG
            atomicMax(&sm[c * KSEG + s4.x], __float_as_int(v.x + BIAS));
            atomicMax(&sm[c * KSEG + s4.y], __float_as_int(v.y + BIAS));
            atomicMax(&sm[c * KSEG + s4.z], __float_as_int(v.z + BIAS));
            atomicMax(&sm[c * KSEG + s4.w], __float_as_int(v.w + BIAS));
        }
    }
    __syncthreads();

    // Merge SMEM partials into global accumulator (d_out viewed as int).
    int* outg = out + (b * CTOT + cg * CGRP) * KSEG;
    #pragma unroll
    for (int i = threadIdx.x; i < CGRP * KSEG; i += 256)
        atomicMax(&outg[i], sm[i]);
}

__global__ void __launch_bounds__(256) sp_decode_kernel(float* __restrict__ out) {
    int i = blockIdx.x * 256 + threadIdx.x;
    // Buffer holds biased float bits (written via int atomics); -inf stays -inf.
    out[i] = out[i] - BIAS;
}

extern "C" void kernel_launch(void* const* d_in, const int* in_sizes, int n_in,
                              void* d_out, int out_size) {
    const float* img = (const float*)d_in[0];   // [4, 64, 512, 512] f32
    const int*   spx = (const int*)d_in[1];     // [4, 512, 512] i32
    float* out = (float*)d_out;                 // [4, 64, 1024] f32 (262144)

    const int n_out = BTOT * CTOT * KSEG;       // 262144

    sp_init_kernel<<<n_out / 256, 256>>>(out);

    dim3 grid(PB, NCG, BTOT);                   // 16 x 8 x 4 = 512 blocks
    sp_main_kernel<<<grid, 256>>>(img, spx, (int*)out);

    sp_decode_kernel<<<n_out / 256, 256>>>(out);
}